// round 5
// baseline (speedup 1.0000x reference)
#include <cuda_runtime.h>
#include <cuda_pipeline_primitives.h>
#include <cuda_bf16.h>
#include <cstdint>

// WeightedSumSessEmbedding: sparse COO [16384 x 1M] @ emb[1M x 64]
// NNZ=819200, row_idx sorted. Inputs: row_idx[i32], col_idx[i32],
// data[f32], num_ids[i32 scalar], embeddings[f32 1M*64]. Output f32 [16384*64].
//
// cp.async pipelined gather: embedding rows staged through a per-warp SMEM
// ring so in-flight gathers are not limited by the register file.

#define EMB_DIM   64
#define CHUNK     64                 // nnz per warp
#define THREADS   128                // 4 warps per block
#define WARPS_PB  (THREADS / 32)
#define GSIZE     4                  // nnz per pipeline group
#define SLOTS     8                  // ring slots per warp (8KB/warp)
#define NGROUPS   (CHUNK / GSIZE)    // 16

__global__ void __launch_bounds__(THREADS, 7)
weighted_seg_sum_kernel(const int* __restrict__ row_idx,
                        const int* __restrict__ col_idx,
                        const float* __restrict__ data,
                        const float* __restrict__ emb,
                        float* __restrict__ out,
                        int nnz)
{
    // [warp][slot][nnz-in-group][lane] float2: 4 * 8 * 4 * 32 * 8B = 32 KB
    __shared__ float2 ring[WARPS_PB][SLOTS][GSIZE][32];

    const int wl   = threadIdx.x >> 5;        // warp within block
    const int lane = threadIdx.x & 31;
    const int warp = blockIdx.x * WARPS_PB + wl;

    const int start = warp * CHUNK;
    if (start >= nnz) return;
    const int end = min(start + CHUNK, nnz);

    const float2* __restrict__ emb2 = reinterpret_cast<const float2*>(emb);

    float2 acc = make_float2(0.0f, 0.0f);
    int cur_row = __ldg(&row_idx[start]);

    #define FLUSH()                                                          \
        do {                                                                 \
            float* o = out + (size_t)cur_row * EMB_DIM + 2 * lane;           \
            atomicAdd(o,     acc.x);                                         \
            atomicAdd(o + 1, acc.y);                                         \
            acc.x = 0.0f; acc.y = 0.0f;                                      \
        } while (0)

    #define STEP(r, w, e)                                                    \
        do {                                                                 \
            if ((r) != cur_row) { FLUSH(); cur_row = (r); }                  \
            acc.x = fmaf((w), (e).x, acc.x);                                 \
            acc.y = fmaf((w), (e).y, acc.y);                                 \
        } while (0)

    if (end - start == CHUNK) {
        // ---- fully pipelined path ----
        // issue(g): async-copy the 4 embedding rows of group g into slot g%SLOTS
        #define ISSUE(g)                                                       \
            do {                                                               \
                const int4 c = __ldg(reinterpret_cast<const int4*>(            \
                                     col_idx + start + (g) * GSIZE));          \
                const int s = (g) & (SLOTS - 1);                               \
                __pipeline_memcpy_async(&ring[wl][s][0][lane],                 \
                                        emb2 + (size_t)c.x * 32 + lane, 8);    \
                __pipeline_memcpy_async(&ring[wl][s][1][lane],                 \
                                        emb2 + (size_t)c.y * 32 + lane, 8);    \
                __pipeline_memcpy_async(&ring[wl][s][2][lane],                 \
                                        emb2 + (size_t)c.z * 32 + lane, 8);    \
                __pipeline_memcpy_async(&ring[wl][s][3][lane],                 \
                                        emb2 + (size_t)c.w * 32 + lane, 8);    \
                __pipeline_commit();                                           \
            } while (0)

        // Prologue: fill SLOTS-1 = 7 groups ahead.
        #pragma unroll
        for (int g = 0; g < SLOTS - 1; ++g) ISSUE(g);

        #pragma unroll 4
        for (int g = 0; g < NGROUPS; ++g) {
            if (g + SLOTS - 1 < NGROUPS) ISSUE(g + SLOTS - 1);
            // Allow SLOTS-1 groups pending -> group g is complete.
            __pipeline_wait_prior(SLOTS - 2);

            const int s = g & (SLOTS - 1);
            const int4   r4 = __ldg(reinterpret_cast<const int4*>(row_idx + start + g * GSIZE));
            const float4 w4 = __ldg(reinterpret_cast<const float4*>(data   + start + g * GSIZE));

            const float2 e0 = ring[wl][s][0][lane];
            const float2 e1 = ring[wl][s][1][lane];
            const float2 e2 = ring[wl][s][2][lane];
            const float2 e3 = ring[wl][s][3][lane];

            STEP(r4.x, w4.x, e0);
            STEP(r4.y, w4.y, e1);
            STEP(r4.z, w4.z, e2);
            STEP(r4.w, w4.w, e3);
        }
        #undef ISSUE
    } else {
        // ---- generic tail path (partial chunk) ----
        for (int i = start; i < end; ++i) {
            const int   r = __ldg(&row_idx[i]);
            const int   c = __ldg(&col_idx[i]);
            const float w = __ldg(&data[i]);
            const float2 e = __ldg(emb2 + (size_t)c * 32 + lane);
            STEP(r, w, e);
        }
    }

    FLUSH();

    #undef STEP
    #undef FLUSH
}

extern "C" void kernel_launch(void* const* d_in, const int* in_sizes, int n_in,
                              void* d_out, int out_size)
{
    const int*   row_idx = (const int*)  d_in[0];
    const int*   col_idx = (const int*)  d_in[1];
    const float* data    = (const float*)d_in[2];
    const float* emb     = (const float*)d_in[4];
    float*       out     = (float*)d_out;

    const int nnz = in_sizes[0];

    cudaMemsetAsync(out, 0, (size_t)out_size * sizeof(float));

    const int warps  = (nnz + CHUNK - 1) / CHUNK;
    const int blocks = (warps + WARPS_PB - 1) / WARPS_PB;
    weighted_seg_sum_kernel<<<blocks, THREADS>>>(
        row_idx, col_idx, data, emb, out, nnz);
}